// round 5
// baseline (speedup 1.0000x reference)
#include <cuda_runtime.h>
#include <cstdint>

// Stacked LSTM (2 layers, D=H=6) + softmax, sm_103a.
// One lane per (batch element, hidden unit); weights in registers; h broadcast
// via shfl; layers software-pipelined (1-step skew). Gate dot products use
// packed fma.rn.f32x2 (FFMA2): gate pairs (i,f) and (g,o) share one 64-bit
// accumulator, halving FMA-pipe slots per step. Sigmoid gates pre-halved so
// sigmoid = tanh.approx + FFMA.

#define FULLMASK 0xFFFFFFFFu
typedef unsigned long long ull;

__device__ __forceinline__ float ex2f(float x) {
    float r; asm("ex2.approx.f32 %0, %1;" : "=f"(r) : "f"(x)); return r;
}
__device__ __forceinline__ float rcpf(float x) {
    float r; asm("rcp.approx.f32 %0, %1;" : "=f"(r) : "f"(x)); return r;
}
__device__ __forceinline__ float htanh(float x) {
    float r; asm("tanh.approx.f32 %0, %1;" : "=f"(r) : "f"(x)); return r;
}
__device__ __forceinline__ ull pack2(float lo, float hi) {
    ull r; asm("mov.b64 %0, {%1, %2};" : "=l"(r) : "f"(lo), "f"(hi)); return r;
}
__device__ __forceinline__ ull dup2(float v) {
    ull r; asm("mov.b64 %0, {%1, %1};" : "=l"(r) : "f"(v)); return r;
}
__device__ __forceinline__ void unpack2(ull v, float& lo, float& hi) {
    asm("mov.b64 {%0, %1}, %2;" : "=f"(lo), "=f"(hi) : "l"(v));
}
__device__ __forceinline__ ull ffma2(ull a, ull b, ull c) {
    ull d; asm("fma.rn.f32x2 %0, %1, %2, %3;" : "=l"(d) : "l"(a), "l"(b), "l"(c)); return d;
}

// Given packed pre-activations p01={a_i, a_f} (pre-halved), p23={a_g, a_o(pre-halved)}:
__device__ __forceinline__ void gates_update(ull p01, ull p23, float& c, float& nh) {
    float a0, a1, a2, a3;
    unpack2(p01, a0, a1);
    unpack2(p23, a2, a3);
    float ig = fmaf(0.5f, htanh(a0), 0.5f);
    float fg = fmaf(0.5f, htanh(a1), 0.5f);
    float gg = htanh(a2);
    float og = fmaf(0.5f, htanh(a3), 0.5f);
    c  = fmaf(fg, c, ig * gg);
    nh = og * htanh(c);
}

__global__ __launch_bounds__(128, 1)
void stacked_lstm_kernel(const float* __restrict__ x,
                         const float* __restrict__ Wih0, const float* __restrict__ Whh0,
                         const float* __restrict__ bih0, const float* __restrict__ bhh0,
                         const float* __restrict__ Wih1, const float* __restrict__ Whh1,
                         const float* __restrict__ bih1, const float* __restrict__ bhh1,
                         float* __restrict__ out,
                         int B, int T) {
    const int lane = threadIdx.x & 31;
    const int warp_global = (blockIdx.x * blockDim.x + threadIdx.x) >> 5;
    const int g = lane / 6;          // group within warp (0..4 active)
    const int j = lane - g * 6;      // hidden unit owned by this lane
    const int base = g * 6;
    const int b = warp_global * 5 + g;
    const bool valid = (g < 5) && (b < B);
    const int bc = (b < B) ? b : (B - 1);

    // ---- packed weights: pair (gate0,gate1)=(i,f) and (gate2,gate3)=(g,o) ----
    // i,f,o rows pre-halved (sigmoid via tanh); g full scale.
    ull wi0p01[6], wi0p23[6], wh0p01[6], wh0p23[6];
    ull wi1p01[6], wi1p23[6], wh1p01[6], wh1p23[6];
    ull bz0p01, bz0p23, bz1p01, bz1p23;
    {
        float sc[4] = {0.5f, 0.5f, 1.0f, 0.5f};   // gate order i,f,g,o
        int r0 = j, r1 = 6 + j, r2 = 12 + j, r3 = 18 + j;
        bz0p01 = pack2((bih0[r0] + bhh0[r0]) * sc[0], (bih0[r1] + bhh0[r1]) * sc[1]);
        bz0p23 = pack2((bih0[r2] + bhh0[r2]) * sc[2], (bih0[r3] + bhh0[r3]) * sc[3]);
        bz1p01 = pack2((bih1[r0] + bhh1[r0]) * sc[0], (bih1[r1] + bhh1[r1]) * sc[1]);
        bz1p23 = pack2((bih1[r2] + bhh1[r2]) * sc[2], (bih1[r3] + bhh1[r3]) * sc[3]);
#pragma unroll
        for (int d = 0; d < 6; ++d) {
            wi0p01[d] = pack2(Wih0[r0 * 6 + d] * sc[0], Wih0[r1 * 6 + d] * sc[1]);
            wi0p23[d] = pack2(Wih0[r2 * 6 + d] * sc[2], Wih0[r3 * 6 + d] * sc[3]);
            wh0p01[d] = pack2(Whh0[r0 * 6 + d] * sc[0], Whh0[r1 * 6 + d] * sc[1]);
            wh0p23[d] = pack2(Whh0[r2 * 6 + d] * sc[2], Whh0[r3 * 6 + d] * sc[3]);
            wi1p01[d] = pack2(Wih1[r0 * 6 + d] * sc[0], Wih1[r1 * 6 + d] * sc[1]);
            wi1p23[d] = pack2(Wih1[r2 * 6 + d] * sc[2], Wih1[r3 * 6 + d] * sc[3]);
            wh1p01[d] = pack2(Whh1[r0 * 6 + d] * sc[0], Whh1[r1 * 6 + d] * sc[1]);
            wh1p23[d] = pack2(Whh1[r2 * 6 + d] * sc[2], Whh1[r3 * 6 + d] * sc[3]);
        }
    }

    // ---- state ----
    float c0 = 0.0f, c1 = 0.0f;
    ull hp0[6], hp1[6];          // packed {h,h} broadcasts
    float h1f[6];                // float copy of h1 for softmax
#pragma unroll
    for (int k = 0; k < 6; ++k) { hp0[k] = 0ull; hp1[k] = 0ull; h1f[k] = 0.0f; }

    const float2* xp = reinterpret_cast<const float2*>(x + (size_t)bc * (size_t)T * 6);

    // x-projection (layer0) for current t, computed one step ahead.
    ull xa01, xa23;
    {
        float2 v0 = xp[0], v1 = xp[1], v2 = xp[2];
        float xin[6] = {v0.x, v0.y, v1.x, v1.y, v2.x, v2.y};
        xa01 = bz0p01; xa23 = bz0p23;
#pragma unroll
        for (int d = 0; d < 6; ++d) {
            ull xv = dup2(xin[d]);
            xa01 = ffma2(wi0p01[d], xv, xa01);
            xa23 = ffma2(wi0p23[d], xv, xa23);
        }
    }

    float nh0, nh1;

    // ---- t = 0: layer0 only ----
    {
        ull a01 = xa01, a23 = xa23;
#pragma unroll
        for (int d = 0; d < 6; ++d) {   // h0 is zero, but keep uniform (cheap)
            a01 = ffma2(wh0p01[d], hp0[d], a01);
            a23 = ffma2(wh0p23[d], hp0[d], a23);
        }
        // next x-projection (t=1)
        {
            float2 v0 = xp[3], v1 = xp[4], v2 = xp[5];
            float xin[6] = {v0.x, v0.y, v1.x, v1.y, v2.x, v2.y};
            xa01 = bz0p01; xa23 = bz0p23;
#pragma unroll
            for (int d = 0; d < 6; ++d) {
                ull xv = dup2(xin[d]);
                xa01 = ffma2(wi0p01[d], xv, xa01);
                xa23 = ffma2(wi0p23[d], xv, xa23);
            }
        }
        asm volatile("prefetch.global.L2 [%0];" :: "l"(xp + 3 * 32));
        gates_update(a01, a23, c0, nh0);
#pragma unroll
        for (int k = 0; k < 6; ++k) hp0[k] = dup2(__shfl_sync(FULLMASK, nh0, base + k));
    }

    // ---- main loop: iteration t computes layer0(t) and layer1(t-1) ----
    for (int t = 1; t < T; ++t) {
        // layer1 dots @ t-1: uses hp0 = h0(t-1), hp1 = h1(t-2). Independent of L0 chain.
        ull b01 = bz1p01, b23 = bz1p23;
#pragma unroll
        for (int d = 0; d < 6; ++d) {
            b01 = ffma2(wi1p01[d], hp0[d], b01);
            b23 = ffma2(wi1p23[d], hp0[d], b23);
        }
#pragma unroll
        for (int d = 0; d < 6; ++d) {
            b01 = ffma2(wh1p01[d], hp1[d], b01);
            b23 = ffma2(wh1p23[d], hp1[d], b23);
        }

        // layer0 recurrent dots @ t
        ull a01 = xa01, a23 = xa23;
#pragma unroll
        for (int d = 0; d < 6; ++d) {
            a01 = ffma2(wh0p01[d], hp0[d], a01);
            a23 = ffma2(wh0p23[d], hp0[d], a23);
        }

        // next x-projection (t+1) — no h dependence, hides under tanh/shfl latency
        {
            int tn = (t + 1 < T) ? (t + 1) : t;
            float2 v0 = xp[3 * tn], v1 = xp[3 * tn + 1], v2 = xp[3 * tn + 2];
            float xin[6] = {v0.x, v0.y, v1.x, v1.y, v2.x, v2.y};
            xa01 = bz0p01; xa23 = bz0p23;
#pragma unroll
            for (int d = 0; d < 6; ++d) {
                ull xv = dup2(xin[d]);
                xa01 = ffma2(wi0p01[d], xv, xa01);
                xa23 = ffma2(wi0p23[d], xv, xa23);
            }
        }
        if (t + 32 < T)
            asm volatile("prefetch.global.L2 [%0];" :: "l"(xp + 3 * (t + 32)));

        gates_update(a01, a23, c0, nh0);   // layer0 @ t
        gates_update(b01, b23, c1, nh1);   // layer1 @ t-1

#pragma unroll
        for (int k = 0; k < 6; ++k) hp0[k] = dup2(__shfl_sync(FULLMASK, nh0, base + k));
#pragma unroll
        for (int k = 0; k < 6; ++k) {
            float hv = __shfl_sync(FULLMASK, nh1, base + k);
            hp1[k] = dup2(hv);
            h1f[k] = hv;
        }
    }

    // ---- final skewed layer1 step @ t = T-1 ----
    {
        ull b01 = bz1p01, b23 = bz1p23;
#pragma unroll
        for (int d = 0; d < 6; ++d) {
            b01 = ffma2(wi1p01[d], hp0[d], b01);
            b23 = ffma2(wi1p23[d], hp0[d], b23);
        }
#pragma unroll
        for (int d = 0; d < 6; ++d) {
            b01 = ffma2(wh1p01[d], hp1[d], b01);
            b23 = ffma2(wh1p23[d], hp1[d], b23);
        }
        gates_update(b01, b23, c1, nh1);
#pragma unroll
        for (int k = 0; k < 6; ++k) h1f[k] = __shfl_sync(FULLMASK, nh1, base + k);
    }

    // ---- softmax over 6 units; lane j writes out[b, j] ----
    if (valid) {
        float m = h1f[0];
#pragma unroll
        for (int k = 1; k < 6; ++k) m = fmaxf(m, h1f[k]);
        float s = 0.0f;
#pragma unroll
        for (int k = 0; k < 6; ++k) s += ex2f(1.4426950408889634f * (h1f[k] - m));
        float e = ex2f(1.4426950408889634f * (h1f[j] - m));
        out[b * 6 + j] = e * rcpf(s);
    }
}

extern "C" void kernel_launch(void* const* d_in, const int* in_sizes, int n_in,
                              void* d_out, int out_size) {
    const float* x    = (const float*)d_in[0];
    const float* Wih0 = (const float*)d_in[1];
    const float* Whh0 = (const float*)d_in[2];
    const float* bih0 = (const float*)d_in[3];
    const float* bhh0 = (const float*)d_in[4];
    const float* Wih1 = (const float*)d_in[5];
    const float* Whh1 = (const float*)d_in[6];
    const float* bih1 = (const float*)d_in[7];
    const float* bhh1 = (const float*)d_in[8];
    float* out = (float*)d_out;

    int B = out_size / 6;
    int T = (int)((long long)in_sizes[0] / ((long long)B * 6));

    int warps = (B + 4) / 5;
    int blocks = (warps + 3) / 4;
    stacked_lstm_kernel<<<blocks, 128>>>(x, Wih0, Whh0, bih0, bhh0,
                                         Wih1, Whh1, bih1, bhh1, out, B, T);
}